// round 10
// baseline (speedup 1.0000x reference)
#include <cuda_runtime.h>

#define N_BOX   1024
#define N_CLS   80
#define MAX_OUT 100
#define THREADS 256

__device__ int g_res[N_CLS * MAX_OUT];
__device__ int g_cnt[N_CLS];

// One block per class: stable argsort by (-score, index) via bitonic sort on
// composite keys, greedy NMS with cutoff + 100-kept early exit.
__global__ __launch_bounds__(THREADS) void nms_kernel(
    const float* __restrict__ boxes,   // [N_BOX, 4] (y1,x1,y2,x2)
    const float* __restrict__ scores)  // [N_CLS, N_BOX]
{
    const int c   = blockIdx.x;
    const int tid = threadIdx.x;

    __shared__ unsigned long long keys[N_BOX];
    __shared__ float y1s[N_BOX], x1s[N_BOX], y2s[N_BOX], x2s[N_BOX], ars[N_BOX];
    __shared__ int keep[N_BOX];
    __shared__ int res_s[MAX_OUT];
    __shared__ int s_cut;

    // Composite keys: ascending == (score desc, index asc) == reference's
    // stable argsort(-scores). Non-negative floats are bit-order-monotone.
    const float* sc = scores + (size_t)c * N_BOX;
    for (int t = tid; t < N_BOX; t += THREADS) {
        unsigned int bits = __float_as_uint(sc[t]);
        keys[t] = ((unsigned long long)(~bits) << 32) | (unsigned int)t;
    }
    for (int t = tid; t < MAX_OUT; t += THREADS) res_s[t] = -1;
    if (tid == 0) s_cut = 0;
    __syncthreads();

    // Bitonic sort ascending (keys unique: index lives in the low bits).
    for (int k = 2; k <= N_BOX; k <<= 1) {
        for (int j = k >> 1; j > 0; j >>= 1) {
            for (int t = tid; t < N_BOX; t += THREADS) {
                int ixj = t ^ j;
                if (ixj > t) {
                    bool up = ((t & k) == 0);
                    unsigned long long a = keys[t], b = keys[ixj];
                    if ((a > b) == up) { keys[t] = b; keys[ixj] = a; }
                }
            }
            __syncthreads();
        }
    }

    // Gather boxes in sorted order; keep = (score > 0.5). Exact-rounding
    // intrinsics mirror the reference's single-rounded ops.
    for (int t = tid; t < N_BOX; t += THREADS) {
        unsigned long long k = keys[t];
        int o = (int)(k & 0xFFFFFFFFull);
        float y1 = boxes[4*o+0], x1 = boxes[4*o+1];
        float y2 = boxes[4*o+2], x2 = boxes[4*o+3];
        y1s[t] = y1; x1s[t] = x1; y2s[t] = y2; x2s[t] = x2;
        ars[t] = __fmul_rn(__fsub_rn(y2, y1), __fsub_rn(x2, x1));
        float s = __uint_as_float(~(unsigned int)(k >> 32));
        keep[t] = (s > 0.5f) ? 1 : 0;
    }
    __syncthreads();

    // Initially-kept items are a prefix (scores sorted descending).
    for (int t = tid; t < N_BOX; t += THREADS)
        if (keep[t] && (t == N_BOX - 1 || !keep[t + 1])) s_cut = t + 1;
    __syncthreads();
    const int cutoff = s_cut;

    // Greedy NMS; early exit at 100 kept (rank >= 100 is discarded).
    int rank = 0;  // uniform across the block
    for (int i = 0; i < cutoff && rank < MAX_OUT; ++i) {
        if (keep[i]) {
            const float y1i = y1s[i], x1i = x1s[i], y2i = y2s[i], x2i = x2s[i];
            const float ai  = ars[i];
            for (int j = i + 1 + tid; j < cutoff; j += THREADS) {
                if (keep[j]) {
                    float ih = fmaxf(__fsub_rn(fminf(y2i, y2s[j]),
                                               fmaxf(y1i, y1s[j])), 0.0f);
                    float iw = fmaxf(__fsub_rn(fminf(x2i, x2s[j]),
                                               fmaxf(x1i, x1s[j])), 0.0f);
                    float inter = __fmul_rn(ih, iw);
                    float uni   = __fsub_rn(__fadd_rn(ai, ars[j]), inter);
                    if (__fdiv_rn(inter, uni) > 0.5f) keep[j] = 0;  // NaN>0.5 false
                }
            }
            if (tid == 0) res_s[rank] = (int)(keys[i] & 0xFFFFFFFFull);
            rank++;
        }
        __syncthreads();
    }
    __syncthreads();

    for (int t = tid; t < MAX_OUT; t += THREADS)
        g_res[c * MAX_OUT + t] = res_s[t];
    if (tid == 0) g_cnt[c] = rank;
}

// Compact into d_out — *** STORED AS FLOAT32 ***. All row values (0, c, idx)
// are small ints, exactly representable in fp32. Zero fill is bit-identical
// in either dtype, so this is the only line of behavior that changes.
__global__ __launch_bounds__(256) void compact_kernel(float* __restrict__ out,
                                                      int out_size)
{
    __shared__ int offs[N_CLS + 1];
    const int tid = threadIdx.x;

    if (tid == 0) {
        int acc = 0;
        for (int c = 0; c < N_CLS; ++c) { offs[c] = acc; acc += g_cnt[c]; }
        offs[N_CLS] = acc;
    }
    __syncthreads();

    for (int i = tid; i < out_size; i += 256) out[i] = 0.0f;
    __syncthreads();

    for (int e = tid; e < N_CLS * MAX_OUT; e += 256) {
        int c = e / MAX_OUT;
        int k = e - c * MAX_OUT;
        if (k < g_cnt[c]) {                 // kept entries are a prefix
            int p = offs[c] + k;
            out[3 * p + 0] = 0.0f;          // batch index (B == 1)
            out[3 * p + 1] = (float)c;
            out[3 * p + 2] = (float)g_res[e];
        }
    }
}

extern "C" void kernel_launch(void* const* d_in, const int* in_sizes, int n_in,
                              void* d_out, int out_size)
{
    // Metadata order: boxes (4096 elems) then scores (81920 elems); swap only
    // if sizes clearly indicate the reverse.
    const float* boxes  = (const float*)d_in[0];
    const float* scores = (const float*)(n_in > 1 ? d_in[1] : d_in[0]);
    if (n_in > 1 && in_sizes[0] > in_sizes[1]) {
        const float* t = boxes; boxes = scores; scores = t;
    }

    nms_kernel<<<N_CLS, THREADS>>>(boxes, scores);
    compact_kernel<<<1, 256>>>((float*)d_out, out_size);
}